// round 2
// baseline (speedup 1.0000x reference)
#include <cuda_runtime.h>
#include <math.h>

// Problem constants
#define Bc  2
#define Sc  2048
#define Dc  1024
#define Hc  16
#define HDc 64
#define BSc (Bc * Sc)   // 4096 rows for the projection GEMMs

// Scratch (device globals; allocation inside kernel_launch is forbidden)
__device__ float g_q[(size_t)Bc * Sc * Dc];
__device__ float g_k[(size_t)Bc * Sc * Dc];
__device__ float g_v[(size_t)Bc * Sc * Dc];
__device__ float g_ctx[(size_t)Bc * Sc * Dc];
// Fallback attn scratch in case the harness output holds only `out`
__device__ float g_attn_scratch[(size_t)Bc * Hc * Sc * Sc];

// ---------------------------------------------------------------------------
// GEMM + bias: C[M,N] = A[M,K] @ W[K,N] + b[N]
// 64x64 output tile, BK=16, 256 threads, 4x4 microtile, vectorized LDS.
// ---------------------------------------------------------------------------
__global__ void gemm_bias_kernel(const float* __restrict__ A,
                                 const float* __restrict__ W,
                                 const float* __restrict__ bias,
                                 float* __restrict__ C,
                                 int M, int N, int K) {
    __shared__ float As[16][68];  // [k][m], padded (272B rows keep 16B align)
    __shared__ float Bs[16][64];  // [k][n]

    const int tid = threadIdx.x;
    const int tx = tid & 15;      // n microtile
    const int ty = tid >> 4;      // m microtile
    const int m0 = blockIdx.x << 6;
    const int n0 = blockIdx.y << 6;

    float acc[4][4] = {};

    for (int k0 = 0; k0 < K; k0 += 16) {
        // Load A tile 64x16 -> As[k][m] (transposed for float4 compute reads)
#pragma unroll
        for (int i = 0; i < 4; i++) {
            int e = tid + i * 256;           // 0..1023
            int r = e >> 4, c = e & 15;      // r = m row, c = k col
            As[c][r] = A[(size_t)(m0 + r) * K + k0 + c];
        }
        // Load W tile 16x64 -> Bs[k][n]
#pragma unroll
        for (int i = 0; i < 4; i++) {
            int e = tid + i * 256;
            int r = e >> 6, c = e & 63;      // r = k row, c = n col
            Bs[r][c] = W[(size_t)(k0 + r) * N + n0 + c];
        }
        __syncthreads();

#pragma unroll
        for (int kk = 0; kk < 16; kk++) {
            float4 a4 = *(const float4*)&As[kk][ty * 4];
            float4 b4 = *(const float4*)&Bs[kk][tx * 4];
            float av[4] = {a4.x, a4.y, a4.z, a4.w};
            float bv[4] = {b4.x, b4.y, b4.z, b4.w};
#pragma unroll
            for (int i = 0; i < 4; i++)
#pragma unroll
                for (int j = 0; j < 4; j++)
                    acc[i][j] = fmaf(av[i], bv[j], acc[i][j]);
        }
        __syncthreads();
    }

#pragma unroll
    for (int i = 0; i < 4; i++) {
        const int row = m0 + ty * 4 + i;
        float4 o;
        o.x = acc[i][0] + bias[n0 + tx * 4 + 0];
        o.y = acc[i][1] + bias[n0 + tx * 4 + 1];
        o.z = acc[i][2] + bias[n0 + tx * 4 + 2];
        o.w = acc[i][3] + bias[n0 + tx * 4 + 3];
        *(float4*)&C[(size_t)row * N + n0 + tx * 4] = o;
    }
}

// ---------------------------------------------------------------------------
// Fused attention for one (b, h, 64-query tile).
// Pass 1: score GEMM (QK^T * scale) -> raw scores to global attn + online m,l
// Pass 2: read raw scores, normalize+write p in place, accumulate P@V -> ctx
// Dynamic smem: 3 buffers of 64x68 floats = 52,224 B.
// ---------------------------------------------------------------------------
#define ALD 68   // padded leading dim (keeps float4 alignment, breaks bank conflicts)

__global__ void attn_kernel(float* __restrict__ attn) {
    extern __shared__ float sh[];
    float* Qt  = sh;                 // [d][q]  (d-major Q, for vectorized reads over q)
    float* Bsh = sh + 64 * ALD;      // pass1: Kt[d][k]; pass2: Vs[k][d]
    float* Ssh = sh + 2 * 64 * ALD;  // pass1: S[q][k];  pass2: Pt[k][q]

    const int b  = blockIdx.z;
    const int h  = blockIdx.y;
    const int q0 = blockIdx.x << 6;
    const int tid = threadIdx.x;
    const int tx = tid & 15;         // GEMM map: key/dim microtile
    const int ty = tid >> 4;         // GEMM map: query microtile
    const int qr = tid >> 2;         // row map: query row 0..63
    const int g  = tid & 3;          // row map: 4 lanes per row
    const float scale = 0.125f;      // 1/sqrt(64)

    float* attn_base = attn + (((size_t)b * Hc + h) * Sc + q0) * Sc;

    // Load Q tile transposed: Qt[d][q]
#pragma unroll
    for (int i = 0; i < 16; i++) {
        int e = tid + i * 256;
        int r = e >> 6, c = e & 63;  // r = query, c = dim
        Qt[c * ALD + r] = g_q[((size_t)b * Sc + q0 + r) * Dc + h * HDc + c];
    }
    __syncthreads();

    float m = -INFINITY, l = 0.0f;

    // ---------------- Pass 1: scores + online softmax stats ----------------
    for (int k0 = 0; k0 < Sc; k0 += 64) {
        // Load K tile transposed: Kt[d][k]
#pragma unroll
        for (int i = 0; i < 16; i++) {
            int e = tid + i * 256;
            int r = e >> 6, c = e & 63;  // r = key, c = dim
            Bsh[c * ALD + r] = g_k[((size_t)b * Sc + k0 + r) * Dc + h * HDc + c];
        }
        __syncthreads();

        // 64x64x64 score GEMM, 4x4 microtile
        float s[4][4] = {};
#pragma unroll
        for (int d = 0; d < 64; d++) {
            float4 a4 = *(const float4*)&Qt[d * ALD + ty * 4];
            float4 b4 = *(const float4*)&Bsh[d * ALD + tx * 4];
            float av[4] = {a4.x, a4.y, a4.z, a4.w};
            float bv[4] = {b4.x, b4.y, b4.z, b4.w};
#pragma unroll
            for (int i = 0; i < 4; i++)
#pragma unroll
                for (int j = 0; j < 4; j++)
                    s[i][j] = fmaf(av[i], bv[j], s[i][j]);
        }
        // Scale + store raw scores to smem (for stats) and global (for pass 2)
#pragma unroll
        for (int i = 0; i < 4; i++) {
            float4 v;
            v.x = s[i][0] * scale;
            v.y = s[i][1] * scale;
            v.z = s[i][2] * scale;
            v.w = s[i][3] * scale;
            *(float4*)&Ssh[(ty * 4 + i) * ALD + tx * 4] = v;
            *(float4*)&attn_base[(size_t)(ty * 4 + i) * Sc + k0 + tx * 4] = v;
        }
        __syncthreads();

        // Online (m, l) update. Each row handled by 4 lanes (g = 0..3).
        float sv[16];
        float tmax = -INFINITY;
#pragma unroll
        for (int i = 0; i < 16; i++) {
            sv[i] = Ssh[qr * ALD + g * 16 + i];
            tmax = fmaxf(tmax, sv[i]);
        }
        tmax = fmaxf(tmax, __shfl_xor_sync(0xffffffffu, tmax, 1));
        tmax = fmaxf(tmax, __shfl_xor_sync(0xffffffffu, tmax, 2));
        const float m_new = fmaxf(m, tmax);
        float lsum = 0.0f;
#pragma unroll
        for (int i = 0; i < 16; i++) lsum += __expf(sv[i] - m_new);
        lsum += __shfl_xor_sync(0xffffffffu, lsum, 1);
        lsum += __shfl_xor_sync(0xffffffffu, lsum, 2);
        l = l * __expf(m - m_new) + lsum;
        m = m_new;
        __syncthreads();
    }

    const float inv_l = 1.0f / l;

    // ---------------- Pass 2: normalize attn + P @ V -----------------------
    float acc[4][4] = {};
    for (int k0 = 0; k0 < Sc; k0 += 64) {
        // Load V tile: Vs[k][d]
#pragma unroll
        for (int i = 0; i < 16; i++) {
            int e = tid + i * 256;
            int r = e >> 6, c = e & 63;  // r = key, c = dim
            Bsh[r * ALD + c] = g_v[((size_t)b * Sc + k0 + r) * Dc + h * HDc + c];
        }
        // Read raw scores (written by this same thread in pass 1), normalize,
        // write p back to global, and stash transposed Pt[k][q] for the GEMM.
#pragma unroll
        for (int i = 0; i < 4; i++) {
            const int kb = g * 16 + i * 4;
            float4 s4 = *(const float4*)&attn_base[(size_t)qr * Sc + k0 + kb];
            float4 p4;
            p4.x = __expf(s4.x - m) * inv_l;
            p4.y = __expf(s4.y - m) * inv_l;
            p4.z = __expf(s4.z - m) * inv_l;
            p4.w = __expf(s4.w - m) * inv_l;
            *(float4*)&attn_base[(size_t)qr * Sc + k0 + kb] = p4;
            Ssh[(kb + 0) * ALD + qr] = p4.x;
            Ssh[(kb + 1) * ALD + qr] = p4.y;
            Ssh[(kb + 2) * ALD + qr] = p4.z;
            Ssh[(kb + 3) * ALD + qr] = p4.w;
        }
        __syncthreads();

        // out[q][d] += P[q][k] * V[k][d], 4x4 microtile (ty=q, tx=d)
#pragma unroll
        for (int k = 0; k < 64; k++) {
            float4 a4 = *(const float4*)&Ssh[k * ALD + ty * 4];   // Pt[k][q]
            float4 b4 = *(const float4*)&Bsh[k * ALD + tx * 4];   // Vs[k][d]
            float av[4] = {a4.x, a4.y, a4.z, a4.w};
            float bv[4] = {b4.x, b4.y, b4.z, b4.w};
#pragma unroll
            for (int i = 0; i < 4; i++)
#pragma unroll
                for (int j = 0; j < 4; j++)
                    acc[i][j] = fmaf(av[i], bv[j], acc[i][j]);
        }
        __syncthreads();
    }

    // Write context (layout [B,S,D] with head h at cols h*64..)
#pragma unroll
    for (int i = 0; i < 4; i++) {
        float4 v = {acc[i][0], acc[i][1], acc[i][2], acc[i][3]};
        *(float4*)&g_ctx[((size_t)b * Sc + q0 + ty * 4 + i) * Dc + h * HDc + tx * 4] = v;
    }
}

// ---------------------------------------------------------------------------
extern "C" void kernel_launch(void* const* d_in, const int* in_sizes, int n_in,
                              void* d_out, int out_size) {
    const float* query = (const float*)d_in[0];
    const float* key_  = (const float*)d_in[1];
    const float* value = (const float*)d_in[2];
    const float* Wq = (const float*)d_in[3];
    const float* bq = (const float*)d_in[4];
    const float* Wk = (const float*)d_in[5];
    const float* bk = (const float*)d_in[6];
    const float* Wv = (const float*)d_in[7];
    const float* bv = (const float*)d_in[8];
    const float* Wo = (const float*)d_in[9];
    const float* bo = (const float*)d_in[10];
    float* out = (float*)d_out;

    float *dq, *dk, *dv, *dctx;
    cudaGetSymbolAddress((void**)&dq,  g_q);
    cudaGetSymbolAddress((void**)&dk,  g_k);
    cudaGetSymbolAddress((void**)&dv,  g_v);
    cudaGetSymbolAddress((void**)&dctx, g_ctx);

    const size_t OUT_ELEMS  = (size_t)Bc * Sc * Dc;           // 4,194,304
    const size_t ATTN_ELEMS = (size_t)Bc * Hc * Sc * Sc;      // 134,217,728
    float* attn_ptr;
    if ((size_t)out_size >= OUT_ELEMS + ATTN_ELEMS) {
        attn_ptr = out + OUT_ELEMS;   // output = [out | attn]
    } else {
        cudaGetSymbolAddress((void**)&attn_ptr, g_attn_scratch);
    }

    // Unconditional (no static guards per harness contract); host-side API,
    // not captured into the graph.
    cudaFuncSetAttribute(attn_kernel,
                         cudaFuncAttributeMaxDynamicSharedMemorySize,
                         3 * 64 * ALD * sizeof(float));

    dim3 ggrid(BSc / 64, Dc / 64);  // 64 x 16

    // Q/K/V projections
    gemm_bias_kernel<<<ggrid, 256>>>(query, Wq, bq, dq, BSc, Dc, Dc);
    gemm_bias_kernel<<<ggrid, 256>>>(key_,  Wk, bk, dk, BSc, Dc, Dc);
    gemm_bias_kernel<<<ggrid, 256>>>(value, Wv, bv, dv, BSc, Dc, Dc);

    // Attention (writes attn probabilities + ctx)
    attn_kernel<<<dim3(Sc / 64, Hc, Bc), 256, 3 * 64 * ALD * sizeof(float)>>>(attn_ptr);

    // Output projection
    gemm_bias_kernel<<<ggrid, 256>>>(dctx, Wo, bo, out, BSc, Dc, Dc);
}